// round 16
// baseline (speedup 1.0000x reference)
#include <cuda_runtime.h>
#include <cuda_fp16.h>
#include <cstdint>

#define Hd   1024
#define Bb   16
#define Ss   512
#define Kk   32
#define Ee   1024
#define NCAT 3072

// ---------------- scratch ----------------------------------------------------
__device__ __half g_Xh[512*Hd];          // full_nodes fp16 [512][1024]
__device__ __half g_Wh[Hd*NCAT];         // Wcat fp16 [k][n]
__device__ __half g_W2h[Hd*2048];        // [nafW | clsW] fp16 [k][n]
__device__ __half g_X2h[Bb*Hd];          // cls tokens fp16
__device__ float g_node_hidden[512*Hd];
__device__ float g_Aj[512*Hd];           // edge bias folded in
__device__ float g_Ai[512*Hd];
__device__ float g_cls_hidden[Bb*Hd];
__device__ float g_invconst[2];
__device__ int   g_n[Bb];

// ---------------- helpers ----------------------------------------------------
__device__ __forceinline__ float tanh_fast(float x) {
    float e = __expf(2.0f * x);
    return 1.0f - __fdividef(2.0f, e + 1.0f);
}

__device__ __forceinline__ uint32_t smem_u32(const void* p) {
    uint32_t a;
    asm("{ .reg .u64 t; cvta.to.shared.u64 t, %1; cvt.u32.u64 %0, t; }" : "=r"(a) : "l"(p));
    return a;
}

__device__ __forceinline__ void cp16(uint32_t saddr, const void* g) {
    asm volatile("cp.async.cg.shared.global [%0], [%1], 16;" :: "r"(saddr), "l"(g));
}
__device__ __forceinline__ void cp_commit() {
    asm volatile("cp.async.commit_group;");
}
template <int N>
__device__ __forceinline__ void cp_wait() {
    asm volatile("cp.async.wait_group %0;" :: "n"(N));
}

__device__ __forceinline__ void ldsm_x4(uint32_t& r0, uint32_t& r1, uint32_t& r2,
                                        uint32_t& r3, uint32_t addr) {
    asm volatile("ldmatrix.sync.aligned.m8n8.x4.shared.b16 {%0,%1,%2,%3}, [%4];"
                 : "=r"(r0), "=r"(r1), "=r"(r2), "=r"(r3) : "r"(addr));
}
__device__ __forceinline__ void ldsm_x2t(uint32_t& r0, uint32_t& r1, uint32_t addr) {
    asm volatile("ldmatrix.sync.aligned.m8n8.x2.trans.shared.b16 {%0,%1}, [%2];"
                 : "=r"(r0), "=r"(r1) : "r"(addr));
}
__device__ __forceinline__ void mma16816h(float* d, const uint32_t* a, const uint32_t* b) {
    asm volatile(
        "mma.sync.aligned.m16n8k16.row.col.f32.f16.f16.f32 "
        "{%0,%1,%2,%3}, {%4,%5,%6,%7}, {%8,%9}, {%0,%1,%2,%3};"
        : "+f"(d[0]), "+f"(d[1]), "+f"(d[2]), "+f"(d[3])
        : "r"(a[0]), "r"(a[1]), "r"(a[2]), "r"(a[3]), "r"(b[0]), "r"(b[1]));
}

__device__ __forceinline__ void block_reduce2(float& a0, float& a1, float* red) {
    #pragma unroll
    for (int o = 16; o > 0; o >>= 1) {
        a0 += __shfl_down_sync(0xffffffffu, a0, o);
        a1 += __shfl_down_sync(0xffffffffu, a1, o);
    }
    int w = threadIdx.x >> 5;
    if ((threadIdx.x & 31) == 0) { red[2*w] = a0; red[2*w+1] = a1; }
    __syncthreads();
    if (threadIdx.x == 0) {
        a0 = red[0]; a1 = red[1];
        for (int w2 = 1; w2 < (int)(blockDim.x >> 5); w2++) {
            a0 += red[2*w2]; a1 += red[2*w2+1];
        }
    }
}

__device__ __forceinline__ void warp_reduce2(float& a0, float& a1) {
    #pragma unroll
    for (int o = 16; o > 0; o >>= 1) {
        a0 += __shfl_down_sync(0xffffffffu, a0, o);
        a1 += __shfl_down_sync(0xffffffffu, a1, o);
    }
}

__device__ __forceinline__ uint2 pack4(float x, float y, float z, float w) {
    uint2 o;
    *(__half2*)&o.x = __floats2half2_rn(x, y);
    *(__half2*)&o.y = __floats2half2_rn(z, w);
    return o;
}

// ======== 1. k_prep — streaming, high-MLP =========================
// blocks: [0,512) meta; [512,1536) Wcat rows; [1536,2560) W2 rows;
//         [2560,2576) cls-token convert; 2576 invconst.
__global__ __launch_bounds__(256) void k_prep(const float* __restrict__ seq,
                                              const int* __restrict__ P,
                                              const float* __restrict__ nodeW,
                                              const float* __restrict__ eW,
                                              const float* __restrict__ eb,
                                              const float* __restrict__ eoW,
                                              const float* __restrict__ eob,
                                              const float* __restrict__ nafW,
                                              const float* __restrict__ clsW) {
    __shared__ float red[16];
    int blk = blockIdx.x;
    int t   = threadIdx.x;

    if (blk < 512) {
        // ---- meta: segment mean (b,k); thread owns one float4 column ----
        int k = blk & 31, b = blk >> 5;
        int n = 0;
        #pragma unroll
        for (int j = 0; j < Kk - 1; j++) n += (P[b*Kk + 1 + j] > 0);
        if (k == 0 && t == 0) g_n[b] = n;
        long rowO = (long)(b*Kk + k) * Hd;
        if (k < n) {
            int end   = P[b*Kk + 1 + k];
            int start = (k == 0) ? 1 : (P[b*Kk + k] + 1);
            float inv = 1.0f / (float)(end - start + 1);
            const float4* src = (const float4*)(seq + ((long)b*Ss + start)*Hd) + t;
            float sx = 0.f, sy = 0.f, sz = 0.f, sw = 0.f;
            int len = end - start + 1;
            int p = 0;
            for (; p + 2 <= len; p += 2) {           // 2 independent loads
                float4 a = src[(long)p*256];
                float4 c = src[(long)(p+1)*256];
                sx += a.x + c.x; sy += a.y + c.y;
                sz += a.z + c.z; sw += a.w + c.w;
            }
            if (p < len) {
                float4 a = src[(long)p*256];
                sx += a.x; sy += a.y; sz += a.z; sw += a.w;
            }
            *(uint2*)&g_Xh[rowO + t*4] = pack4(sx*inv, sy*inv, sz*inv, sw*inv);
        } else if (k > n) {
            *(uint2*)&g_Xh[rowO + t*4] = make_uint2(0u, 0u);
        }
        return;
    }

    if (blk < 1536) {
        // ---- Wcat row k: [node | W0+W2 | W1-W2], single float4 per thread ----
        int k = blk - 512;
        int i = t*4;
        float4 a  = *(const float4*)&nodeW[(long)k*Hd + i];
        float4 b0 = *(const float4*)&eW[(long)k*Hd + i];
        float4 b1 = *(const float4*)&eW[(long)(Hd + k)*Hd + i];
        float4 b2 = *(const float4*)&eW[(long)(2*Hd + k)*Hd + i];
        __half* dst = g_Wh + (long)k*NCAT;
        *(uint2*)&dst[i]        = pack4(a.x, a.y, a.z, a.w);
        *(uint2*)&dst[Hd + i]   = pack4(b0.x + b2.x, b0.y + b2.y, b0.z + b2.z, b0.w + b2.w);
        *(uint2*)&dst[2*Hd + i] = pack4(b1.x - b2.x, b1.y - b2.y, b1.z - b2.z, b1.w - b2.w);
        return;
    }

    if (blk < 2560) {
        // ---- W2 row k: [nafW | clsW], single float4 per thread ----
        int k = blk - 1536;
        int i = t*4;
        float4 a = *(const float4*)&nafW[(long)k*Hd + i];
        float4 c = *(const float4*)&clsW[(long)k*Hd + i];
        __half* dst = g_W2h + (long)k*2048;
        *(uint2*)&dst[i]      = pack4(a.x, a.y, a.z, a.w);
        *(uint2*)&dst[Hd + i] = pack4(c.x, c.y, c.z, c.w);
        return;
    }

    if (blk < 2576) {
        // ---- cls token -> fp16 ----
        int b = blk - 2560;
        int i = t*4;
        float4 v = *(const float4*)&seq[(long)b*Ss*Hd + i];
        *(uint2*)&g_X2h[b*Hd + i] = pack4(v.x, v.y, v.z, v.w);
        return;
    }

    // ---- invalid-edge constant ----
    {
        float a0 = 0.f, a1 = 0.f;
        #pragma unroll
        for (int u = 0; u < Hd/256; u++) {
            int h = t + u*256;
            float v = tanh_fast(eb[h]);
            a0 = fmaf(v, eoW[2*h  ], a0);
            a1 = fmaf(v, eoW[2*h+1], a1);
        }
        block_reduce2(a0, a1, red);
        if (t == 0) { g_invconst[0] = a0 + eob[0]; g_invconst[1] = a1 + eob[1]; }
    }
}

// ======== 2. k_gemv2: [naf|cls] = cls_tok(16x1024) @ W2(1024x2048) ==========
#define BROW 272
#define G2_A_OFF 0
#define G2_B_OFF 1280
#define G2_STAGE (1280 + 32*BROW)
__global__ __launch_bounds__(128) void k_gemv2(const float* __restrict__ nafb,
                                               const float* __restrict__ clsb) {
    extern __shared__ __align__(16) char sm2[];
    int tid = threadIdx.x, wid = tid >> 5, lane = tid & 31;
    const char* gA = (const char*)g_X2h;
    const char* gB = (const char*)g_W2h + blockIdx.x*256;
    uint32_t smb = smem_u32(sm2);

    auto load_stage = [&](int ch, int st) {
        uint32_t sb = smb + st*G2_STAGE;
        if (tid < 64) {
            int r = tid >> 2, c = (tid & 3)*16;
            cp16(sb + G2_A_OFF + r*80 + c, gA + (long)r*2048 + ch*64 + c);
        }
        #pragma unroll
        for (int i = 0; i < 4; i++) {
            int j = tid + i*128;
            int r = j >> 4, c = (j & 15)*16;
            cp16(sb + G2_B_OFF + r*BROW + c, gB + (long)(ch*32 + r)*4096 + c);
        }
    };

    float acc[4][4];
    #pragma unroll
    for (int nt = 0; nt < 4; nt++)
        #pragma unroll
        for (int q = 0; q < 4; q++) acc[nt][q] = 0.0f;

    int brow = (lane & 7) + ((lane >> 3) & 1)*8;

    load_stage(0, 0); cp_commit();
    load_stage(1, 1); cp_commit();
    load_stage(2, 2); cp_commit();

    for (int ch = 0; ch < 32; ch++) {
        cp_wait<2>();
        __syncthreads();
        uint32_t sbase = smb + (ch & 3)*G2_STAGE;
        #pragma unroll
        for (int ks = 0; ks < 2; ks++) {
            uint32_t a[4];
            uint32_t ao = G2_A_OFF + (uint32_t)((lane & 15)*80 + ks*32 + (lane >> 4)*16);
            ldsm_x4(a[0], a[1], a[2], a[3], sbase + ao);
            #pragma unroll
            for (int nt = 0; nt < 4; nt++) {
                uint32_t bo = G2_B_OFF + (uint32_t)((ks*16 + brow)*BROW + wid*64 + nt*16);
                uint32_t b0, b1;
                ldsm_x2t(b0, b1, sbase + bo);
                uint32_t bf[2] = {b0, b1};
                mma16816h(acc[nt], a, bf);
            }
        }
        if (ch + 3 < 32) load_stage(ch + 3, (ch + 3) & 3);
        cp_commit();
    }

    int g = lane >> 2, t = lane & 3;
    bool is_cls = blockIdx.x >= 8;
    #pragma unroll
    for (int nt = 0; nt < 4; nt++) {
        int colg = blockIdx.x*128 + wid*32 + nt*8 + t*2;
        #pragma unroll
        for (int half = 0; half < 2; half++) {
            int b = g + half*8;
            float v0 = acc[nt][half*2 + 0];
            float v1 = acc[nt][half*2 + 1];
            if (!is_cls) {
                int col = colg;
                float n0 = v0 + nafb[col], n1 = v1 + nafb[col+1];
                int slot = g_n[b];
                *(__half2*)&g_Xh[(long)(b*Kk + slot)*Hd + col] = __floats2half2_rn(n0, n1);
            } else {
                int col = colg - 1024;
                g_cls_hidden[b*Hd + col]     = tanh_fast(v0 + clsb[col]);
                g_cls_hidden[b*Hd + col + 1] = tanh_fast(v1 + clsb[col+1]);
            }
        }
    }
}

// ======== 3. fp16 tensor GEMM, trans-B, 4-stage cp.async ====================
#define A_OFF 0
#define B_OFF 5120
#define STAGE_B (5120 + 32*BROW)
__global__ __launch_bounds__(128) void k_gemm(const float* __restrict__ node_b,
                                              const float* __restrict__ edge_b) {
    extern __shared__ __align__(16) char sm[];

    int tid  = threadIdx.x;
    int wid  = tid >> 5, lane = tid & 31;
    int wm   = wid & 1;
    int wn   = wid >> 1;
    int bn   = blockIdx.x, bm = blockIdx.y;

    const char* gX = (const char*)g_Xh + (long)bm*64*2048;
    const char* gW = (const char*)g_Wh + bn*256;
    uint32_t smb = smem_u32(sm);

    auto load_stage = [&](int ch, int st) {
        uint32_t sb = smb + st*STAGE_B;
        #pragma unroll
        for (int i = 0; i < 6; i++) {
            int idx = tid + i*128;
            if (idx < 256) {
                int r = idx >> 2, c = (idx & 3)*16;
                cp16(sb + A_OFF + r*80 + c, gX + (long)r*2048 + ch*64 + c);
            } else {
                int j = idx - 256;
                int r = j >> 4, c = (j & 15)*16;
                cp16(sb + B_OFF + r*BROW + c, gW + (long)(ch*32 + r)*6144 + c);
            }
        }
    };

    float acc[2][8][4];
    #pragma unroll
    for (int mt = 0; mt < 2; mt++)
        #pragma unroll
        for (int nt = 0; nt < 8; nt++)
            #pragma unroll
            for (int q = 0; q < 4; q++) acc[mt][nt][q] = 0.0f;

    int a_row  = wm*32 + (lane & 15);
    int a_koff = (lane >> 4) * 16;
    int brow   = (lane & 7) + ((lane >> 3) & 1)*8;

    load_stage(0, 0); cp_commit();
    load_stage(1, 1); cp_commit();
    load_stage(2, 2); cp_commit();

    for (int ch = 0; ch < 32; ch++) {
        cp_wait<2>();
        __syncthreads();
        uint32_t sbase = smb + (ch & 3)*STAGE_B;

        #pragma unroll
        for (int ks = 0; ks < 2; ks++) {
            uint32_t a[2][4];
            #pragma unroll
            for (int mt = 0; mt < 2; mt++) {
                uint32_t ao = (uint32_t)((a_row + mt*16)*80 + ks*32 + a_koff);
                ldsm_x4(a[mt][0], a[mt][1], a[mt][2], a[mt][3], sbase + A_OFF + ao);
            }
            #pragma unroll
            for (int nt = 0; nt < 8; nt++) {
                uint32_t bo = (uint32_t)((ks*16 + brow)*BROW + (wn*64 + nt*8)*2);
                uint32_t b0, b1;
                ldsm_x2t(b0, b1, sbase + B_OFF + bo);
                uint32_t bf[2] = {b0, b1};
                #pragma unroll
                for (int mt = 0; mt < 2; mt++)
                    mma16816h(acc[mt][nt], a[mt], bf);
            }
        }
        if (ch + 3 < 32) load_stage(ch + 3, (ch + 3) & 3);
        cp_commit();
    }

    // ---- epilogue: fp32 outputs ----
    int g = lane >> 2, t = lane & 3;
    int region = bn >> 3;
    #pragma unroll
    for (int mt = 0; mt < 2; mt++) {
        #pragma unroll
        for (int nt = 0; nt < 8; nt++) {
            int col = bn*128 + wn*64 + nt*8 + t*2;
            #pragma unroll
            for (int half = 0; half < 2; half++) {
                int row = bm*64 + wm*32 + mt*16 + g + half*8;
                float v0 = acc[mt][nt][half*2 + 0];
                float v1 = acc[mt][nt][half*2 + 1];
                if (region == 0) {
                    float2 o = make_float2(tanh_fast(v0 + node_b[col]),
                                           tanh_fast(v1 + node_b[col+1]));
                    *(float2*)&g_node_hidden[(long)row*Hd + col] = o;
                } else if (region == 1) {
                    int h = col - Hd;
                    float2 o = make_float2(v0 + edge_b[h], v1 + edge_b[h+1]);
                    *(float2*)&g_Aj[(long)row*Hd + h] = o;
                } else {
                    int h = col - 2*Hd;
                    *(float2*)&g_Ai[(long)row*Hd + h] = make_float2(v0, v1);
                }
            }
        }
    }
}

// ======== 4. k_post: heads + invalid fill + 2-edge-per-warp logits ==========
// blocks: [0,66) heads; [66,82) invalid fill; [82, 82+1024) edge groups of 16.
__global__ __launch_bounds__(256) void k_post(const float* __restrict__ clsoW,
                                              const float* __restrict__ clsob,
                                              const float* __restrict__ noW,
                                              const float* __restrict__ nob,
                                              const float* __restrict__ eoW,
                                              const float* __restrict__ eob,
                                              float* __restrict__ out) {
    __shared__ __half2 sWh[Hd];      // packed (w0,w1) per h, 4 KB
    int blk = blockIdx.x;
    int tid = threadIdx.x;
    int wid = tid >> 5, lane = tid & 31;
    const long EBASE = 32 + Bb*Kk*2;

    if (blk < 66) {
        int r = blk*8 + wid;           // 0..527
        float a0 = 0.f, a1 = 0.f;
        const float *src, *oW, *ob;
        long obase;
        if (r < 16) { src = g_cls_hidden + (long)r*Hd; oW = clsoW; ob = clsob; obase = r*2; }
        else { int rr = r - 16; src = g_node_hidden + (long)rr*Hd; oW = noW; ob = nob; obase = 32 + rr*2; }
        #pragma unroll
        for (int s = 0; s < 8; s++) {
            int h = s*128 + lane*4;
            float4 v  = *(const float4*)&src[h];
            float4 wa = *(const float4*)&oW[2*h];
            float4 wb = *(const float4*)&oW[2*h + 4];
            a0 = fmaf(v.x, wa.x, a0); a1 = fmaf(v.x, wa.y, a1);
            a0 = fmaf(v.y, wa.z, a0); a1 = fmaf(v.y, wa.w, a1);
            a0 = fmaf(v.z, wb.x, a0); a1 = fmaf(v.z, wb.y, a1);
            a0 = fmaf(v.w, wb.z, a0); a1 = fmaf(v.w, wb.w, a1);
        }
        warp_reduce2(a0, a1);
        if (lane == 0) { out[obase] = a0 + ob[0]; out[obase + 1] = a1 + ob[1]; }
        return;
    }

    if (blk < 82) {
        int b = blk - 66;
        int m = g_n[b] + 1, mm = m*m;
        float c0 = g_invconst[0], c1 = g_invconst[1];
        long base = EBASE + (long)b*Ee*2;
        for (int idx = mm*2 + tid; idx < 2048; idx += 256)
            out[base + idx] = (idx & 1) ? c1 : c0;
        return;
    }

    // ---- edges: block = (b, group of 16); warp handles 2 edges ----
    int id = blk - 82;               // 0..1023
    int b  = id >> 6;
    int e0 = (id & 63) * 16;
    int m = g_n[b] + 1, mm = m*m;
    if (e0 >= mm) return;

    #pragma unroll
    for (int u = 0; u < 4; u++) {
        int h = tid + u*256;
        float2 w = ((const float2*)eoW)[h];
        sWh[h] = __floats2half2_rn(w.x, w.y);
    }
    __syncthreads();

    int eA = e0 + wid*2;
    int eB = eA + 1;
    bool vA = eA < mm, vB = eB < mm;
    if (!vA) return;
    int eBc = vB ? eB : eA;
    int iA = eA / m, jA = eA - iA*m;
    int iB = eBc / m, jB = eBc - iB*m;
    const float4* ajA = (const float4*)&g_Aj[(long)(b*Kk + jA)*Hd];
    const float4* aiA = (const float4*)&g_Ai[(long)(b*Kk + iA)*Hd];
    const float4* ajB = (const float4*)&g_Aj[(long)(b*Kk + jB)*Hd];
    const float4* aiB = (const float4*)&g_Ai[(long)(b*Kk + iB)*Hd];

    float a0A = 0.f, a1A = 0.f, a0B = 0.f, a1B = 0.f;
    #pragma unroll
    for (int s = 0; s < 8; s++) {
        int q = s*32 + lane;
        float4 xA = ajA[q], yA = aiA[q];
        float4 xB = ajB[q], yB = aiB[q];
        uint4 wv = ((const uint4*)sWh)[q];
        const uint32_t wr[4] = {wv.x, wv.y, wv.z, wv.w};
        const float xa[4] = {xA.x, xA.y, xA.z, xA.w};
        const float ya[4] = {yA.x, yA.y, yA.z, yA.w};
        const float xb[4] = {xB.x, xB.y, xB.z, xB.w};
        const float yb[4] = {yB.x, yB.y, yB.z, yB.w};
        #pragma unroll
        for (int p = 0; p < 4; p++) {
            float2 w = __half22float2(*(const __half2*)&wr[p]);
            float tA = tanh_fast(xa[p] + ya[p]);
            float tB = tanh_fast(xb[p] + yb[p]);
            a0A = fmaf(tA, w.x, a0A); a1A = fmaf(tA, w.y, a1A);
            a0B = fmaf(tB, w.x, a0B); a1B = fmaf(tB, w.y, a1B);
        }
    }
    warp_reduce2(a0A, a1A);
    warp_reduce2(a0B, a1B);
    if (lane == 0) {
        long baseA = EBASE + ((long)b*Ee + eA)*2;
        out[baseA]     = a0A + eob[0];
        out[baseA + 1] = a1A + eob[1];
        if (vB) {
            long baseB = baseA + 2;
            out[baseB]     = a0B + eob[0];
            out[baseB + 1] = a1B + eob[1];
        }
    }
}

// ---------------------------------------------------------------------------
extern "C" void kernel_launch(void* const* d_in, const int* in_sizes, int n_in,
                              void* d_out, int out_size) {
    const float* seq   = (const float*)d_in[0];
    const int*   P     = (const int*)d_in[1];
    const float* nafW  = (const float*)d_in[2];
    const float* nafb  = (const float*)d_in[3];
    const float* clsW  = (const float*)d_in[4];
    const float* clsb  = (const float*)d_in[5];
    const float* clsoW = (const float*)d_in[6];
    const float* clsob = (const float*)d_in[7];
    const float* ndW   = (const float*)d_in[8];
    const float* ndb   = (const float*)d_in[9];
    const float* noW   = (const float*)d_in[10];
    const float* nob   = (const float*)d_in[11];
    const float* edW   = (const float*)d_in[12];
    const float* edb   = (const float*)d_in[13];
    const float* eoW   = (const float*)d_in[14];
    const float* eob   = (const float*)d_in[15];
    float* out = (float*)d_out;

    cudaFuncSetAttribute(k_gemm,  cudaFuncAttributeMaxDynamicSharedMemorySize, 4*STAGE_B);
    cudaFuncSetAttribute(k_gemv2, cudaFuncAttributeMaxDynamicSharedMemorySize, 4*G2_STAGE);

    k_prep<<<2577, 256>>>(seq, P, ndW, edW, edb, eoW, eob, nafW, clsW);     // idx 0
    k_gemv2<<<16, 128, 4*G2_STAGE>>>(nafb, clsb);                           // idx 1
    k_gemm<<<dim3(NCAT/128, 512/64), 128, 4*STAGE_B>>>(ndb, edb);           // idx 2
    k_post<<<82 + 1024, 256>>>(clsoW, clsob, noW, nob, eoW, eob, out);      // idx 3
}

// round 17
// speedup vs baseline: 1.4597x; 1.4597x over previous
#include <cuda_runtime.h>
#include <cuda_fp16.h>
#include <cstdint>

#define Hd   1024
#define Bb   16
#define Ss   512
#define Kk   32
#define Ee   1024
#define NCAT 3072

// ---------------- scratch ----------------------------------------------------
__device__ __half g_Xh[512*Hd];          // full_nodes fp16 [512][1024]
__device__ __half g_Wh[Hd*NCAT];         // Wcat fp16 [k][n]
__device__ __half g_W2h[Hd*2048];        // [nafW | clsW] fp16 [k][n]
__device__ __half g_X2h[Bb*Hd];          // cls tokens fp16
__device__ float g_node_hidden[512*Hd];
__device__ float g_Aj[512*Hd];           // edge bias folded in
__device__ float g_Ai[512*Hd];
__device__ float g_cls_hidden[Bb*Hd];
__device__ float g_invconst[2];
__device__ int   g_n[Bb];

// ---------------- helpers ----------------------------------------------------
__device__ __forceinline__ float tanh_fast(float x) {
    float e = __expf(2.0f * x);
    return 1.0f - __fdividef(2.0f, e + 1.0f);
}

__device__ __forceinline__ uint32_t smem_u32(const void* p) {
    uint32_t a;
    asm("{ .reg .u64 t; cvta.to.shared.u64 t, %1; cvt.u32.u64 %0, t; }" : "=r"(a) : "l"(p));
    return a;
}

__device__ __forceinline__ void cp16(uint32_t saddr, const void* g) {
    asm volatile("cp.async.cg.shared.global [%0], [%1], 16;" :: "r"(saddr), "l"(g));
}
__device__ __forceinline__ void cp_commit() {
    asm volatile("cp.async.commit_group;");
}
template <int N>
__device__ __forceinline__ void cp_wait() {
    asm volatile("cp.async.wait_group %0;" :: "n"(N));
}

__device__ __forceinline__ void ldsm_x4(uint32_t& r0, uint32_t& r1, uint32_t& r2,
                                        uint32_t& r3, uint32_t addr) {
    asm volatile("ldmatrix.sync.aligned.m8n8.x4.shared.b16 {%0,%1,%2,%3}, [%4];"
                 : "=r"(r0), "=r"(r1), "=r"(r2), "=r"(r3) : "r"(addr));
}
__device__ __forceinline__ void ldsm_x2t(uint32_t& r0, uint32_t& r1, uint32_t addr) {
    asm volatile("ldmatrix.sync.aligned.m8n8.x2.trans.shared.b16 {%0,%1}, [%2];"
                 : "=r"(r0), "=r"(r1) : "r"(addr));
}
__device__ __forceinline__ void mma16816h(float* d, const uint32_t* a, const uint32_t* b) {
    asm volatile(
        "mma.sync.aligned.m16n8k16.row.col.f32.f16.f16.f32 "
        "{%0,%1,%2,%3}, {%4,%5,%6,%7}, {%8,%9}, {%0,%1,%2,%3};"
        : "+f"(d[0]), "+f"(d[1]), "+f"(d[2]), "+f"(d[3])
        : "r"(a[0]), "r"(a[1]), "r"(a[2]), "r"(a[3]), "r"(b[0]), "r"(b[1]));
}

__device__ __forceinline__ void block_reduce2(float& a0, float& a1, float* red) {
    #pragma unroll
    for (int o = 16; o > 0; o >>= 1) {
        a0 += __shfl_down_sync(0xffffffffu, a0, o);
        a1 += __shfl_down_sync(0xffffffffu, a1, o);
    }
    int w = threadIdx.x >> 5;
    if ((threadIdx.x & 31) == 0) { red[2*w] = a0; red[2*w+1] = a1; }
    __syncthreads();
    if (threadIdx.x == 0) {
        a0 = red[0]; a1 = red[1];
        for (int w2 = 1; w2 < (int)(blockDim.x >> 5); w2++) {
            a0 += red[2*w2]; a1 += red[2*w2+1];
        }
    }
}

__device__ __forceinline__ void warp_reduce2(float& a0, float& a1) {
    #pragma unroll
    for (int o = 16; o > 0; o >>= 1) {
        a0 += __shfl_down_sync(0xffffffffu, a0, o);
        a1 += __shfl_down_sync(0xffffffffu, a1, o);
    }
}

__device__ __forceinline__ uint2 pack4(float x, float y, float z, float w) {
    uint2 o;
    *(__half2*)&o.x = __floats2half2_rn(x, y);
    *(__half2*)&o.y = __floats2half2_rn(z, w);
    return o;
}

// ======== 1. k_prep — streaming, high-MLP =========================
// blocks: [0,512) meta; [512,1536) Wcat rows; [1536,2560) W2 rows;
//         [2560,2576) cls-token convert; 2576 invconst.
__global__ __launch_bounds__(256) void k_prep(const float* __restrict__ seq,
                                              const int* __restrict__ P,
                                              const float* __restrict__ nodeW,
                                              const float* __restrict__ eW,
                                              const float* __restrict__ eb,
                                              const float* __restrict__ eoW,
                                              const float* __restrict__ eob,
                                              const float* __restrict__ nafW,
                                              const float* __restrict__ clsW) {
    __shared__ float red[16];
    int blk = blockIdx.x;
    int t   = threadIdx.x;

    if (blk < 512) {
        // ---- meta: segment mean (b,k); thread owns one float4 column ----
        int k = blk & 31, b = blk >> 5;
        int n = 0;
        #pragma unroll
        for (int j = 0; j < Kk - 1; j++) n += (P[b*Kk + 1 + j] > 0);
        if (k == 0 && t == 0) g_n[b] = n;
        long rowO = (long)(b*Kk + k) * Hd;
        if (k < n) {
            int end   = P[b*Kk + 1 + k];
            int start = (k == 0) ? 1 : (P[b*Kk + k] + 1);
            float inv = 1.0f / (float)(end - start + 1);
            const float4* src = (const float4*)(seq + ((long)b*Ss + start)*Hd) + t;
            float sx = 0.f, sy = 0.f, sz = 0.f, sw = 0.f;
            int len = end - start + 1;
            int p = 0;
            for (; p + 4 <= len; p += 4) {           // 4 independent loads in flight
                float4 a = src[(long)p*256];
                float4 c = src[(long)(p+1)*256];
                float4 d = src[(long)(p+2)*256];
                float4 e = src[(long)(p+3)*256];
                sx += (a.x + c.x) + (d.x + e.x);
                sy += (a.y + c.y) + (d.y + e.y);
                sz += (a.z + c.z) + (d.z + e.z);
                sw += (a.w + c.w) + (d.w + e.w);
            }
            for (; p < len; p++) {
                float4 a = src[(long)p*256];
                sx += a.x; sy += a.y; sz += a.z; sw += a.w;
            }
            *(uint2*)&g_Xh[rowO + t*4] = pack4(sx*inv, sy*inv, sz*inv, sw*inv);
        } else if (k > n) {
            *(uint2*)&g_Xh[rowO + t*4] = make_uint2(0u, 0u);
        }
        return;
    }

    if (blk < 1536) {
        // ---- Wcat row k: [node | W0+W2 | W1-W2], single float4 per thread ----
        int k = blk - 512;
        int i = t*4;
        float4 a  = *(const float4*)&nodeW[(long)k*Hd + i];
        float4 b0 = *(const float4*)&eW[(long)k*Hd + i];
        float4 b1 = *(const float4*)&eW[(long)(Hd + k)*Hd + i];
        float4 b2 = *(const float4*)&eW[(long)(2*Hd + k)*Hd + i];
        __half* dst = g_Wh + (long)k*NCAT;
        *(uint2*)&dst[i]        = pack4(a.x, a.y, a.z, a.w);
        *(uint2*)&dst[Hd + i]   = pack4(b0.x + b2.x, b0.y + b2.y, b0.z + b2.z, b0.w + b2.w);
        *(uint2*)&dst[2*Hd + i] = pack4(b1.x - b2.x, b1.y - b2.y, b1.z - b2.z, b1.w - b2.w);
        return;
    }

    if (blk < 2560) {
        // ---- W2 row k: [nafW | clsW], single float4 per thread ----
        int k = blk - 1536;
        int i = t*4;
        float4 a = *(const float4*)&nafW[(long)k*Hd + i];
        float4 c = *(const float4*)&clsW[(long)k*Hd + i];
        __half* dst = g_W2h + (long)k*2048;
        *(uint2*)&dst[i]      = pack4(a.x, a.y, a.z, a.w);
        *(uint2*)&dst[Hd + i] = pack4(c.x, c.y, c.z, c.w);
        return;
    }

    if (blk < 2576) {
        // ---- cls token -> fp16 ----
        int b = blk - 2560;
        int i = t*4;
        float4 v = *(const float4*)&seq[(long)b*Ss*Hd + i];
        *(uint2*)&g_X2h[b*Hd + i] = pack4(v.x, v.y, v.z, v.w);
        return;
    }

    // ---- invalid-edge constant ----
    {
        float a0 = 0.f, a1 = 0.f;
        #pragma unroll
        for (int u = 0; u < Hd/256; u++) {
            int h = t + u*256;
            float v = tanh_fast(eb[h]);
            a0 = fmaf(v, eoW[2*h  ], a0);
            a1 = fmaf(v, eoW[2*h+1], a1);
        }
        block_reduce2(a0, a1, red);
        if (t == 0) { g_invconst[0] = a0 + eob[0]; g_invconst[1] = a1 + eob[1]; }
    }
}

// ======== 2. k_gemv2: [naf|cls] = cls_tok(16x1024) @ W2(1024x2048) ==========
#define BROW 272
#define G2_A_OFF 0
#define G2_B_OFF 1280
#define G2_STAGE (1280 + 32*BROW)
__global__ __launch_bounds__(128) void k_gemv2(const float* __restrict__ nafb,
                                               const float* __restrict__ clsb) {
    extern __shared__ __align__(16) char sm2[];
    int tid = threadIdx.x, wid = tid >> 5, lane = tid & 31;
    const char* gA = (const char*)g_X2h;
    const char* gB = (const char*)g_W2h + blockIdx.x*256;
    uint32_t smb = smem_u32(sm2);

    auto load_stage = [&](int ch, int st) {
        uint32_t sb = smb + st*G2_STAGE;
        if (tid < 64) {
            int r = tid >> 2, c = (tid & 3)*16;
            cp16(sb + G2_A_OFF + r*80 + c, gA + (long)r*2048 + ch*64 + c);
        }
        #pragma unroll
        for (int i = 0; i < 4; i++) {
            int j = tid + i*128;
            int r = j >> 4, c = (j & 15)*16;
            cp16(sb + G2_B_OFF + r*BROW + c, gB + (long)(ch*32 + r)*4096 + c);
        }
    };

    float acc[4][4];
    #pragma unroll
    for (int nt = 0; nt < 4; nt++)
        #pragma unroll
        for (int q = 0; q < 4; q++) acc[nt][q] = 0.0f;

    int brow = (lane & 7) + ((lane >> 3) & 1)*8;

    load_stage(0, 0); cp_commit();
    load_stage(1, 1); cp_commit();
    load_stage(2, 2); cp_commit();

    for (int ch = 0; ch < 32; ch++) {
        cp_wait<2>();
        __syncthreads();
        uint32_t sbase = smb + (ch & 3)*G2_STAGE;
        #pragma unroll
        for (int ks = 0; ks < 2; ks++) {
            uint32_t a[4];
            uint32_t ao = G2_A_OFF + (uint32_t)((lane & 15)*80 + ks*32 + (lane >> 4)*16);
            ldsm_x4(a[0], a[1], a[2], a[3], sbase + ao);
            #pragma unroll
            for (int nt = 0; nt < 4; nt++) {
                uint32_t bo = G2_B_OFF + (uint32_t)((ks*16 + brow)*BROW + wid*64 + nt*16);
                uint32_t b0, b1;
                ldsm_x2t(b0, b1, sbase + bo);
                uint32_t bf[2] = {b0, b1};
                mma16816h(acc[nt], a, bf);
            }
        }
        if (ch + 3 < 32) load_stage(ch + 3, (ch + 3) & 3);
        cp_commit();
    }

    int g = lane >> 2, t = lane & 3;
    bool is_cls = blockIdx.x >= 8;
    #pragma unroll
    for (int nt = 0; nt < 4; nt++) {
        int colg = blockIdx.x*128 + wid*32 + nt*8 + t*2;
        #pragma unroll
        for (int half = 0; half < 2; half++) {
            int b = g + half*8;
            float v0 = acc[nt][half*2 + 0];
            float v1 = acc[nt][half*2 + 1];
            if (!is_cls) {
                int col = colg;
                float n0 = v0 + nafb[col], n1 = v1 + nafb[col+1];
                int slot = g_n[b];
                *(__half2*)&g_Xh[(long)(b*Kk + slot)*Hd + col] = __floats2half2_rn(n0, n1);
            } else {
                int col = colg - 1024;
                g_cls_hidden[b*Hd + col]     = tanh_fast(v0 + clsb[col]);
                g_cls_hidden[b*Hd + col + 1] = tanh_fast(v1 + clsb[col+1]);
            }
        }
    }
}

// ======== 3. fp16 tensor GEMM, trans-B, 4-stage cp.async ====================
#define A_OFF 0
#define B_OFF 5120
#define STAGE_B (5120 + 32*BROW)
__global__ __launch_bounds__(128) void k_gemm(const float* __restrict__ node_b,
                                              const float* __restrict__ edge_b) {
    extern __shared__ __align__(16) char sm[];

    int tid  = threadIdx.x;
    int wid  = tid >> 5, lane = tid & 31;
    int wm   = wid & 1;
    int wn   = wid >> 1;
    int bn   = blockIdx.x, bm = blockIdx.y;

    const char* gX = (const char*)g_Xh + (long)bm*64*2048;
    const char* gW = (const char*)g_Wh + bn*256;
    uint32_t smb = smem_u32(sm);

    auto load_stage = [&](int ch, int st) {
        uint32_t sb = smb + st*STAGE_B;
        #pragma unroll
        for (int i = 0; i < 6; i++) {
            int idx = tid + i*128;
            if (idx < 256) {
                int r = idx >> 2, c = (idx & 3)*16;
                cp16(sb + A_OFF + r*80 + c, gX + (long)r*2048 + ch*64 + c);
            } else {
                int j = idx - 256;
                int r = j >> 4, c = (j & 15)*16;
                cp16(sb + B_OFF + r*BROW + c, gW + (long)(ch*32 + r)*6144 + c);
            }
        }
    };

    float acc[2][8][4];
    #pragma unroll
    for (int mt = 0; mt < 2; mt++)
        #pragma unroll
        for (int nt = 0; nt < 8; nt++)
            #pragma unroll
            for (int q = 0; q < 4; q++) acc[mt][nt][q] = 0.0f;

    int a_row  = wm*32 + (lane & 15);
    int a_koff = (lane >> 4) * 16;
    int brow   = (lane & 7) + ((lane >> 3) & 1)*8;

    load_stage(0, 0); cp_commit();
    load_stage(1, 1); cp_commit();
    load_stage(2, 2); cp_commit();

    for (int ch = 0; ch < 32; ch++) {
        cp_wait<2>();
        __syncthreads();
        uint32_t sbase = smb + (ch & 3)*STAGE_B;

        #pragma unroll
        for (int ks = 0; ks < 2; ks++) {
            uint32_t a[2][4];
            #pragma unroll
            for (int mt = 0; mt < 2; mt++) {
                uint32_t ao = (uint32_t)((a_row + mt*16)*80 + ks*32 + a_koff);
                ldsm_x4(a[mt][0], a[mt][1], a[mt][2], a[mt][3], sbase + A_OFF + ao);
            }
            #pragma unroll
            for (int nt = 0; nt < 8; nt++) {
                uint32_t bo = (uint32_t)((ks*16 + brow)*BROW + (wn*64 + nt*8)*2);
                uint32_t b0, b1;
                ldsm_x2t(b0, b1, sbase + B_OFF + bo);
                uint32_t bf[2] = {b0, b1};
                #pragma unroll
                for (int mt = 0; mt < 2; mt++)
                    mma16816h(acc[mt][nt], a[mt], bf);
            }
        }
        if (ch + 3 < 32) load_stage(ch + 3, (ch + 3) & 3);
        cp_commit();
    }

    // ---- epilogue: fp32 outputs ----
    int g = lane >> 2, t = lane & 3;
    int region = bn >> 3;
    #pragma unroll
    for (int mt = 0; mt < 2; mt++) {
        #pragma unroll
        for (int nt = 0; nt < 8; nt++) {
            int col = bn*128 + wn*64 + nt*8 + t*2;
            #pragma unroll
            for (int half = 0; half < 2; half++) {
                int row = bm*64 + wm*32 + mt*16 + g + half*8;
                float v0 = acc[mt][nt][half*2 + 0];
                float v1 = acc[mt][nt][half*2 + 1];
                if (region == 0) {
                    float2 o = make_float2(tanh_fast(v0 + node_b[col]),
                                           tanh_fast(v1 + node_b[col+1]));
                    *(float2*)&g_node_hidden[(long)row*Hd + col] = o;
                } else if (region == 1) {
                    int h = col - Hd;
                    float2 o = make_float2(v0 + edge_b[h], v1 + edge_b[h+1]);
                    *(float2*)&g_Aj[(long)row*Hd + h] = o;
                } else {
                    int h = col - 2*Hd;
                    *(float2*)&g_Ai[(long)row*Hd + h] = make_float2(v0, v1);
                }
            }
        }
    }
}

// ======== 4. k_post: heads + invalid fill + 2-edge-per-warp logits ==========
// blocks: [0,66) heads; [66,82) invalid fill; [82, 82+1024) edge groups of 16.
__global__ __launch_bounds__(256) void k_post(const float* __restrict__ clsoW,
                                              const float* __restrict__ clsob,
                                              const float* __restrict__ noW,
                                              const float* __restrict__ nob,
                                              const float* __restrict__ eoW,
                                              const float* __restrict__ eob,
                                              float* __restrict__ out) {
    __shared__ __half2 sWh[Hd];      // packed (w0,w1) per h, 4 KB
    int blk = blockIdx.x;
    int tid = threadIdx.x;
    int wid = tid >> 5, lane = tid & 31;
    const long EBASE = 32 + Bb*Kk*2;

    if (blk < 66) {
        int r = blk*8 + wid;           // 0..527
        float a0 = 0.f, a1 = 0.f;
        const float *src, *oW, *ob;
        long obase;
        if (r < 16) { src = g_cls_hidden + (long)r*Hd; oW = clsoW; ob = clsob; obase = r*2; }
        else { int rr = r - 16; src = g_node_hidden + (long)rr*Hd; oW = noW; ob = nob; obase = 32 + rr*2; }
        #pragma unroll
        for (int s = 0; s < 8; s++) {
            int h = s*128 + lane*4;
            float4 v  = *(const float4*)&src[h];
            float4 wa = *(const float4*)&oW[2*h];
            float4 wb = *(const float4*)&oW[2*h + 4];
            a0 = fmaf(v.x, wa.x, a0); a1 = fmaf(v.x, wa.y, a1);
            a0 = fmaf(v.y, wa.z, a0); a1 = fmaf(v.y, wa.w, a1);
            a0 = fmaf(v.z, wb.x, a0); a1 = fmaf(v.z, wb.y, a1);
            a0 = fmaf(v.w, wb.z, a0); a1 = fmaf(v.w, wb.w, a1);
        }
        warp_reduce2(a0, a1);
        if (lane == 0) { out[obase] = a0 + ob[0]; out[obase + 1] = a1 + ob[1]; }
        return;
    }

    if (blk < 82) {
        int b = blk - 66;
        int m = g_n[b] + 1, mm = m*m;
        float c0 = g_invconst[0], c1 = g_invconst[1];
        long base = EBASE + (long)b*Ee*2;
        for (int idx = mm*2 + tid; idx < 2048; idx += 256)
            out[base + idx] = (idx & 1) ? c1 : c0;
        return;
    }

    // ---- edges: block = (b, group of 16); warp handles 2 edges ----
    int id = blk - 82;               // 0..1023
    int b  = id >> 6;
    int e0 = (id & 63) * 16;
    int m = g_n[b] + 1, mm = m*m;
    if (e0 >= mm) return;

    #pragma unroll
    for (int u = 0; u < 4; u++) {
        int h = tid + u*256;
        float2 w = ((const float2*)eoW)[h];
        sWh[h] = __floats2half2_rn(w.x, w.y);
    }
    __syncthreads();

    int eA = e0 + wid*2;
    int eB = eA + 1;
    bool vA = eA < mm, vB = eB < mm;
    if (!vA) return;
    int eBc = vB ? eB : eA;
    int iA = eA / m, jA = eA - iA*m;
    int iB = eBc / m, jB = eBc - iB*m;
    const float4* ajA = (const float4*)&g_Aj[(long)(b*Kk + jA)*Hd];
    const float4* aiA = (const float4*)&g_Ai[(long)(b*Kk + iA)*Hd];
    const float4* ajB = (const float4*)&g_Aj[(long)(b*Kk + jB)*Hd];
    const float4* aiB = (const float4*)&g_Ai[(long)(b*Kk + iB)*Hd];

    float a0A = 0.f, a1A = 0.f, a0B = 0.f, a1B = 0.f;
    #pragma unroll
    for (int s = 0; s < 8; s++) {
        int q = s*32 + lane;
        float4 xA = ajA[q], yA = aiA[q];
        float4 xB = ajB[q], yB = aiB[q];
        uint4 wv = ((const uint4*)sWh)[q];
        const uint32_t wr[4] = {wv.x, wv.y, wv.z, wv.w};
        const float xa[4] = {xA.x, xA.y, xA.z, xA.w};
        const float ya[4] = {yA.x, yA.y, yA.z, yA.w};
        const float xb[4] = {xB.x, xB.y, xB.z, xB.w};
        const float yb[4] = {yB.x, yB.y, yB.z, yB.w};
        #pragma unroll
        for (int p = 0; p < 4; p++) {
            float2 w = __half22float2(*(const __half2*)&wr[p]);
            float tA = tanh_fast(xa[p] + ya[p]);
            float tB = tanh_fast(xb[p] + yb[p]);
            a0A = fmaf(tA, w.x, a0A); a1A = fmaf(tA, w.y, a1A);
            a0B = fmaf(tB, w.x, a0B); a1B = fmaf(tB, w.y, a1B);
        }
    }
    warp_reduce2(a0A, a1A);
    warp_reduce2(a0B, a1B);
    if (lane == 0) {
        long baseA = EBASE + ((long)b*Ee + eA)*2;
        out[baseA]     = a0A + eob[0];
        out[baseA + 1] = a1A + eob[1];
        if (vB) {
            long baseB = baseA + 2;
            out[baseB]     = a0B + eob[0];
            out[baseB + 1] = a1B + eob[1];
        }
    }
}

// ---------------------------------------------------------------------------
extern "C" void kernel_launch(void* const* d_in, const int* in_sizes, int n_in,
                              void* d_out, int out_size) {
    const float* seq   = (const float*)d_in[0];
    const int*   P     = (const int*)d_in[1];
    const float* nafW  = (const float*)d_in[2];
    const float* nafb  = (const float*)d_in[3];
    const float* clsW  = (const float*)d_in[4];
    const float* clsb  = (const float*)d_in[5];
    const float* clsoW = (const float*)d_in[6];
    const float* clsob = (const float*)d_in[7];
    const float* ndW   = (const float*)d_in[8];
    const float* ndb   = (const float*)d_in[9];
    const float* noW   = (const float*)d_in[10];
    const float* nob   = (const float*)d_in[11];
    const float* edW   = (const float*)d_in[12];
    const float* edb   = (const float*)d_in[13];
    const float* eoW   = (const float*)d_in[14];
    const float* eob   = (const float*)d_in[15];
    float* out = (float*)d_out;

    cudaFuncSetAttribute(k_gemm,  cudaFuncAttributeMaxDynamicSharedMemorySize, 4*STAGE_B);
    cudaFuncSetAttribute(k_gemv2, cudaFuncAttributeMaxDynamicSharedMemorySize, 4*G2_STAGE);

    k_prep<<<2577, 256>>>(seq, P, ndW, edW, edb, eoW, eob, nafW, clsW);     // idx 0
    k_gemv2<<<16, 128, 4*G2_STAGE>>>(nafb, clsb);                           // idx 1
    k_gemm<<<dim3(NCAT/128, 512/64), 128, 4*STAGE_B>>>(ndb, edb);           // idx 2
    k_post<<<82 + 1024, 256>>>(clsoW, clsob, noW, nob, eoW, eob, out);      // idx 3
}